// round 1
// baseline (speedup 1.0000x reference)
#include <cuda_runtime.h>
#include <math.h>

#define BB 4
#define CIN 256
#define PP 64
#define HH 128
#define WW 128
#define HWSZ (HH*WW)
#define KK 8
#define BN_EPS 1e-5f

// Scratch (device globals: allocation-free)
__device__ float g_h[BB*PP*HWSZ];      // after 1x1 conv + BN + SiLU
__device__ float g_proj[BB*PP*HWSZ];   // after dw3x3 + BN + SiLU
__device__ float g_mind[BB*HWSZ];      // per-pixel min distance (scaled by 1/(tau+1e-6))
__device__ float g_factor[BB*HWSZ];    // 1 + gamma*attn
__device__ unsigned int g_minbits[BB];
__device__ unsigned int g_maxbits[BB];

__device__ __forceinline__ float sigmoidf_(float x){ return 1.0f/(1.0f+__expf(-x)); }
__device__ __forceinline__ float siluf_(float x){ return x*sigmoidf_(x); }

// ---------------------------------------------------------------- init
__global__ void k_init(){
    int t = threadIdx.x;
    if (t < BB){ g_minbits[t] = 0x7F7FFFFFu; g_maxbits[t] = 0u; }
}

// ---------------------------------------------------------------- k1: 1x1 conv (GEMM 64x16384x256) + BN + SiLU
__global__ __launch_bounds__(256) void k1_gemm(const float* __restrict__ x,
                                               const float* __restrict__ w,
                                               const float* __restrict__ bn){
    __shared__ float ws[32][64];        // [k][cout]
    __shared__ float xs[32][128];       // [k][pixel]
    int b    = blockIdx.y;
    int pix0 = blockIdx.x * 128;
    int tid  = threadIdx.x;
    const float* xb = x + (size_t)b*CIN*HWSZ;

    float acc[4][8];
    #pragma unroll
    for (int i=0;i<4;i++)
        #pragma unroll
        for (int j=0;j<8;j++) acc[i][j] = 0.f;

    int ty = tid >> 4, tx = tid & 15;   // 16x16 thread grid: 4 couts x 8 pixels each

    for (int k0 = 0; k0 < CIN; k0 += 32){
        // load W chunk: consecutive tid -> consecutive cout (conflict-free STS)
        #pragma unroll
        for (int i=0;i<8;i++){
            int idx  = tid + i*256;       // 0..2047
            int cout = idx & 63;
            int kk   = idx >> 6;          // 0..31
            ws[kk][cout] = w[cout*CIN + k0 + kk];
        }
        // load X chunk as float4 (fully coalesced 512B per 32 threads)
        #pragma unroll
        for (int i=0;i<4;i++){
            int idx = tid + i*256;        // 0..1023
            int kk  = idx >> 5;           // 0..31
            int p4  = idx & 31;           // 0..31
            *(float4*)&xs[kk][p4*4] = *(const float4*)&xb[(size_t)(k0+kk)*HWSZ + pix0 + p4*4];
        }
        __syncthreads();
        #pragma unroll
        for (int kk=0; kk<32; kk++){
            float4 a  = *(float4*)&ws[kk][ty*4];
            float4 b0 = *(float4*)&xs[kk][tx*8];
            float4 b1 = *(float4*)&xs[kk][tx*8+4];
            float av[4] = {a.x,a.y,a.z,a.w};
            float bv[8] = {b0.x,b0.y,b0.z,b0.w,b1.x,b1.y,b1.z,b1.w};
            #pragma unroll
            for (int i=0;i<4;i++)
                #pragma unroll
                for (int j=0;j<8;j++)
                    acc[i][j] = fmaf(av[i], bv[j], acc[i][j]);
        }
        __syncthreads();
    }
    // epilogue: BN (folded affine) + SiLU
    #pragma unroll
    for (int i=0;i<4;i++){
        int c = ty*4 + i;
        float g  = bn[c], be = bn[PP+c], m = bn[2*PP+c], v = bn[3*PP+c];
        float sc = g * rsqrtf(v + BN_EPS);
        float sh = be - m*sc;
        float o[8];
        #pragma unroll
        for (int j=0;j<8;j++) o[j] = siluf_(fmaf(acc[i][j], sc, sh));
        float* hp = g_h + (size_t)b*PP*HWSZ + (size_t)c*HWSZ + pix0 + tx*8;
        *(float4*)hp     = make_float4(o[0],o[1],o[2],o[3]);
        *(float4*)(hp+4) = make_float4(o[4],o[5],o[6],o[7]);
    }
}

// ---------------------------------------------------------------- k2: depthwise 3x3 (zero pad) + BN + SiLU
__global__ void k2_dw(const float* __restrict__ dw, const float* __restrict__ bn){
    int bc = blockIdx.z;                 // b*64 + c
    int c  = bc & 63;
    int gx = blockIdx.x*32 + threadIdx.x;
    int gy = blockIdx.y*8  + threadIdx.y;
    const float* hp = g_h + (size_t)bc*HWSZ;

    float wv[9];
    #pragma unroll
    for (int i=0;i<9;i++) wv[i] = dw[c*9+i];

    float s = 0.f;
    #pragma unroll
    for (int dy=-1; dy<=1; dy++){
        int yy = gy + dy;
        if ((unsigned)yy < HH){
            #pragma unroll
            for (int dx=-1; dx<=1; dx++){
                int xx = gx + dx;
                if ((unsigned)xx < WW)
                    s = fmaf(wv[(dy+1)*3 + dx+1], hp[yy*WW + xx], s);
            }
        }
    }
    float g  = bn[c], be = bn[PP+c], m = bn[2*PP+c], v = bn[3*PP+c];
    float sc = g * rsqrtf(v + BN_EPS);
    g_proj[(size_t)bc*HWSZ + gy*WW + gx] = siluf_(fmaf(s, sc, be - m*sc));
}

// ---------------------------------------------------------------- k3: min L2 distance to prototypes + per-image min/max
__global__ __launch_bounds__(256) void k3_dist(const float* __restrict__ protos){
    __shared__ float ps[KK][PP];
    __shared__ float pn[KK];
    __shared__ float smin[8], smax[8];
    int b   = blockIdx.y;
    int tid = threadIdx.x;
    int p   = blockIdx.x*256 + tid;

    for (int i = tid; i < KK*PP; i += 256) ps[i/PP][i%PP] = protos[i];
    __syncthreads();
    if (tid < KK){
        float s = 0.f;
        #pragma unroll
        for (int c=0;c<PP;c++) s = fmaf(ps[tid][c], ps[tid][c], s);
        pn[tid] = s;
    }
    __syncthreads();

    const float* fp = g_proj + (size_t)b*PP*HWSZ + p;
    float nf = 0.f, dot[KK];
    #pragma unroll
    for (int k=0;k<KK;k++) dot[k] = 0.f;
    #pragma unroll 4
    for (int c=0;c<PP;c++){
        float fv = fp[(size_t)c*HWSZ];
        nf = fmaf(fv, fv, nf);
        #pragma unroll
        for (int k=0;k<KK;k++) dot[k] = fmaf(fv, ps[k][c], dot[k]);
    }
    float m = 3.4e38f;
    #pragma unroll
    for (int k=0;k<KK;k++) m = fminf(m, nf + pn[k] - 2.f*dot[k]);

    float md = sqrtf(fmaxf(m, 0.f)) * (1.0f/(1.0f + 1e-6f));   // / (TAU + 1e-6), TAU=1
    g_mind[b*HWSZ + p] = md;

    // block reduce min/max then atomics (values >= 0 -> uint ordering valid)
    float wmin = md, wmax = md;
    #pragma unroll
    for (int o=16;o>0;o>>=1){
        wmin = fminf(wmin, __shfl_xor_sync(0xffffffffu, wmin, o));
        wmax = fmaxf(wmax, __shfl_xor_sync(0xffffffffu, wmax, o));
    }
    int wid = tid >> 5, lid = tid & 31;
    if (lid == 0){ smin[wid] = wmin; smax[wid] = wmax; }
    __syncthreads();
    if (tid == 0){
        float bm = smin[0], bM = smax[0];
        #pragma unroll
        for (int i=1;i<8;i++){ bm = fminf(bm, smin[i]); bM = fmaxf(bM, smax[i]); }
        atomicMin(&g_minbits[b], __float_as_uint(bm));
        atomicMax(&g_maxbits[b], __float_as_uint(bM));
    }
}

// ---------------------------------------------------------------- k4: deviation -> two DS-conv branches -> fuse -> sigmoid -> factor
__global__ __launch_bounds__(256) void k4_attn(
        const float* __restrict__ bs_dw, const float* __restrict__ bs_bn1,
        const float* __restrict__ bs_pw, const float* __restrict__ bs_bn2,
        const float* __restrict__ bl_dw, const float* __restrict__ bl_bn1,
        const float* __restrict__ bl_pw, const float* __restrict__ bl_bn2,
        const float* __restrict__ fuse_w, const float* __restrict__ fuse_b,
        const float* __restrict__ gamma){
    __shared__ float sdev[12][36];       // 8x32 tile + 2-halo for 5x5
    int b   = blockIdx.z;
    int gx0 = blockIdx.x*32, gy0 = blockIdx.y*8;
    int tx  = threadIdx.x,  ty  = threadIdx.y;
    int tid = ty*32 + tx;

    float dmin = __uint_as_float(g_minbits[b]);
    float dmax = __uint_as_float(g_maxbits[b]);
    float inv  = 1.0f/(dmax - dmin + 1e-6f);
    const float* mdp = g_mind + b*HWSZ;

    for (int i = tid; i < 12*36; i += 256){
        int ly = i/36, lx = i%36;
        int yy = gy0 - 2 + ly, xx = gx0 - 2 + lx;
        float v = 0.f;                    // zero padding (conv semantics)
        if ((unsigned)yy < HH && (unsigned)xx < WW)
            v = (mdp[yy*WW + xx] - dmin) * inv;
        sdev[ly][lx] = v;
    }
    __syncthreads();

    int cy = ty + 2, cx = tx + 2;
    // branch 1: dw 3x3 -> BN -> SiLU (single channel)
    float t1 = 0.f;
    #pragma unroll
    for (int dy=0;dy<3;dy++)
        #pragma unroll
        for (int dx=0;dx<3;dx++)
            t1 = fmaf(bs_dw[dy*3+dx], sdev[cy+dy-1][cx+dx-1], t1);
    { float g=bs_bn1[0], be=bs_bn1[1], m=bs_bn1[2], v=bs_bn1[3];
      float sc = g*rsqrtf(v+BN_EPS); t1 = siluf_(fmaf(t1, sc, be - m*sc)); }
    // branch 2: dw 5x5 -> BN -> SiLU
    float t2 = 0.f;
    #pragma unroll
    for (int dy=0;dy<5;dy++)
        #pragma unroll
        for (int dx=0;dx<5;dx++)
            t2 = fmaf(bl_dw[dy*5+dx], sdev[cy+dy-2][cx+dx-2], t2);
    { float g=bl_bn1[0], be=bl_bn1[1], m=bl_bn1[2], v=bl_bn1[3];
      float sc = g*rsqrtf(v+BN_EPS); t2 = siluf_(fmaf(t2, sc, be - m*sc)); }

    // pointwise 1->8 + BN + SiLU on each branch, fused 1x1 (16->1), sigmoid
    float logit = fuse_b[0];
    #pragma unroll
    for (int c=0;c<8;c++){
        float g=bs_bn2[c], be=bs_bn2[8+c], m=bs_bn2[16+c], v=bs_bn2[24+c];
        float sc = g*rsqrtf(v+BN_EPS);
        float f1 = siluf_(fmaf(bs_pw[c]*t1, sc, be - m*sc));
        logit = fmaf(fuse_w[c], f1, logit);
    }
    #pragma unroll
    for (int c=0;c<8;c++){
        float g=bl_bn2[c], be=bl_bn2[8+c], m=bl_bn2[16+c], v=bl_bn2[24+c];
        float sc = g*rsqrtf(v+BN_EPS);
        float f2 = siluf_(fmaf(bl_pw[c]*t2, sc, be - m*sc));
        logit = fmaf(fuse_w[8+c], f2, logit);
    }
    int gy = gy0 + ty, gx = gx0 + tx;
    g_factor[b*HWSZ + gy*WW + gx] = 1.0f + gamma[0]*sigmoidf_(logit);
}

// ---------------------------------------------------------------- k5: out = x * factor (broadcast over 256 channels), pure streaming
__global__ __launch_bounds__(256) void k5_apply(const float* __restrict__ x,
                                                float* __restrict__ out){
    size_t i = ((size_t)blockIdx.x*256 + threadIdx.x) * 4;   // element index (fp32), total 2^24
    float4 xv = *(const float4*)(x + i);
    size_t pos = i & (size_t)(HWSZ - 1);                     // i % 16384
    int b      = (int)(i >> 22);                             // i / (256*16384)
    float4 fv = *(const float4*)(g_factor + (size_t)b*HWSZ + pos);
    float4 ov;
    ov.x = xv.x * fv.x;
    ov.y = xv.y * fv.y;
    ov.z = xv.z * fv.z;
    ov.w = xv.w * fv.w;
    *(float4*)(out + i) = ov;
}

// ---------------------------------------------------------------- launch
extern "C" void kernel_launch(void* const* d_in, const int* in_sizes, int n_in,
                              void* d_out, int out_size){
    const float* x      = (const float*)d_in[0];
    const float* fp_w1  = (const float*)d_in[1];
    const float* fp_bn1 = (const float*)d_in[2];
    const float* fp_dw  = (const float*)d_in[3];
    const float* fp_bn2 = (const float*)d_in[4];
    const float* protos = (const float*)d_in[5];
    const float* bs_dw  = (const float*)d_in[6];
    const float* bs_bn1 = (const float*)d_in[7];
    const float* bs_pw  = (const float*)d_in[8];
    const float* bs_bn2 = (const float*)d_in[9];
    const float* bl_dw  = (const float*)d_in[10];
    const float* bl_bn1 = (const float*)d_in[11];
    const float* bl_pw  = (const float*)d_in[12];
    const float* bl_bn2 = (const float*)d_in[13];
    const float* fuse_w = (const float*)d_in[14];
    const float* fuse_b = (const float*)d_in[15];
    const float* gamma  = (const float*)d_in[16];
    float* out = (float*)d_out;

    k_init<<<1, 32>>>();
    k1_gemm<<<dim3(128, BB), 256>>>(x, fp_w1, fp_bn1);
    k2_dw  <<<dim3(4, 16, BB*PP), dim3(32, 8)>>>(fp_dw, fp_bn2);
    k3_dist<<<dim3(64, BB), 256>>>(protos);
    k4_attn<<<dim3(4, 16, BB), dim3(32, 8)>>>(bs_dw, bs_bn1, bs_pw, bs_bn2,
                                              bl_dw, bl_bn1, bl_pw, bl_bn2,
                                              fuse_w, fuse_b, gamma);
    k5_apply<<<(BB*CIN*HWSZ)/4/256, 256>>>(x, out);
}